// round 11
// baseline (speedup 1.0000x reference)
#include <cuda_runtime.h>
#include <cstdint>

// Problem constants (fixed shapes per reference)
#define BB    256
#define VV    128000
#define LL    32
#define NNEG  1024
#define EPSF  1e-8f
#define TMARG 2.0f
#define NTHR  0.1f

// Deterministic scratch
__device__ float        g_partial[BB * 4];
__device__ unsigned int g_count = 0;          // reset by last block -> replay-safe
__device__ __align__(16) int g_sorted[NNEG];  // ascending negative ids

// ---------------------------------------------------------------------------
// Kernel 1: deterministic bitonic sort of the 1024 negative ids (1 CTA).
// Sorted order gives each gather block an ascending-address walk over its
// 512KB sparse row -> DRAM row-buffer locality instead of random activation.
// ---------------------------------------------------------------------------
__global__ __launch_bounds__(1024) void sort_kernel(const int* __restrict__ neg_ids)
{
    __shared__ int s[NNEG];
    const int t = threadIdx.x;
    s[t] = neg_ids[t];
    __syncthreads();

    for (int k = 2; k <= NNEG; k <<= 1) {
        for (int j = k >> 1; j > 0; j >>= 1) {
            const int partner = t ^ j;
            if (partner > t) {
                const bool up = ((t & k) == 0);
                const int a = s[t];
                const int b = s[partner];
                if ((a > b) == up) { s[t] = b; s[partner] = a; }
            }
            __syncthreads();
        }
    }
    g_sorted[t] = s[t];
}

// Scattered gather with L2 evict_last hint (kept from R10; no downside).
__device__ __forceinline__ float ldg_keep(const float* p, unsigned long long pol) {
    float v;
    asm volatile("ld.global.L2::cache_hint.f32 %0, [%1], %2;"
                 : "=f"(v) : "l"(p), "l"(pol));
    return v;
}

// ---------------------------------------------------------------------------
// Kernel 2: one block per batch row, 256 threads, 4 ADJACENT sorted gathers
// per thread (ascending addresses within thread, warp, and block).
// Last block (atomic ticket) does the one-pass final reduce.
// ---------------------------------------------------------------------------
__global__ __launch_bounds__(256) void fused_kernel(
    const float* __restrict__ sparse,
    const int*   __restrict__ ko_ids,
    const int*   __restrict__ ko_len,
    const int*   __restrict__ en_ids,
    const int*   __restrict__ en_len,
    float*       __restrict__ out)
{
    const int b = blockIdx.x;
    const int t = threadIdx.x;
    const float* __restrict__ row = sparse + (size_t)b * VV;

    unsigned long long pol;
    asm volatile("createpolicy.fractional.L2::evict_last.b64 %0, 1.0;" : "=l"(pol));

    // ---- negatives FIRST: 4 adjacent sorted ids per thread ----
    const int4 ids = reinterpret_cast<const int4*>(g_sorted)[t];  // 256*4 = 1024
    const float x0 = ldg_keep(row + ids.x, pol);
    const float x1 = ldg_keep(row + ids.y, pol);
    const float x2 = ldg_keep(row + ids.z, pol);
    const float x3 = ldg_keep(row + ids.w, pol);

    float v_self = 0.0f, v_tgt = 0.0f, v_mar = 0.0f;

    // ---- ko/en terms: warp 0 (t < 32) ----
    if (t < LL) {
        const int kl  = ko_len[b];
        const int el  = en_len[b];
        const int kid = ko_ids[b * LL + t];
        const int eid = en_ids[b * LL + t];
        const float ka = ldg_keep(row + kid, pol);
        const float ea = ldg_keep(row + eid, pol);
        if (t < kl) v_self = -__logf(ka + EPSF);
        if (t < el) {
            v_tgt = -__logf(ea + EPSF);
            v_mar = fmaxf(TMARG - ea, 0.0f);
        }
    }

    float v_neg = fmaxf(x0 - NTHR, 0.0f) + fmaxf(x1 - NTHR, 0.0f)
                + fmaxf(x2 - NTHR, 0.0f) + fmaxf(x3 - NTHR, 0.0f);

    // ---- warp reduction (fixed shuffle order -> deterministic) ----
    #pragma unroll
    for (int off = 16; off > 0; off >>= 1) {
        v_self += __shfl_down_sync(0xFFFFFFFFu, v_self, off);
        v_tgt  += __shfl_down_sync(0xFFFFFFFFu, v_tgt,  off);
        v_mar  += __shfl_down_sync(0xFFFFFFFFu, v_mar,  off);
        v_neg  += __shfl_down_sync(0xFFFFFFFFu, v_neg,  off);
    }

    __shared__ float sh[8][4];
    const int wid = t >> 5;
    if ((t & 31) == 0) {
        sh[wid][0] = v_self;
        sh[wid][1] = v_tgt;
        sh[wid][2] = v_mar;
        sh[wid][3] = v_neg;
    }
    __syncthreads();

    __shared__ bool s_last;
    if (t == 0) {
        float s0 = 0.f, s1 = 0.f, s2 = 0.f, s3 = 0.f;
        #pragma unroll
        for (int w = 0; w < 8; w++) {
            s0 += sh[w][0]; s1 += sh[w][1]; s2 += sh[w][2]; s3 += sh[w][3];
        }
        const float ck = fmaxf((float)ko_len[b], 1.0f);
        const float ce = fmaxf((float)en_len[b], 1.0f);
        // masked_mean: len==0 -> masked sum 0, so s/max(len,1)==0 already
        // matches the jnp.where(length>0, ..., 0) branch.
        g_partial[b * 4 + 0] = s0 / ck;
        g_partial[b * 4 + 1] = s1 / ce;
        g_partial[b * 4 + 2] = s2 / ce;
        g_partial[b * 4 + 3] = s3;          // raw neg sum; scaled below
        __threadfence();
        const unsigned int ticket = atomicAdd(&g_count, 1u);
        s_last = (ticket == BB - 1);
    }
    __syncthreads();

    if (!s_last) return;

    // ---- last block: one-pass final reduce (warp-per-component) ----
    __threadfence();  // acquire all g_partial writes
    {
        const int k    = wid & 3;
        const int h    = wid >> 2;
        const int lane = t & 31;
        float s = 0.0f;
        #pragma unroll
        for (int j = 0; j < 4; j++) {
            const int p = h * 128 + j * 32 + lane;      // 0..255
            s += g_partial[p * 4 + k];
        }
        #pragma unroll
        for (int off = 16; off > 0; off >>= 1)
            s += __shfl_down_sync(0xFFFFFFFFu, s, off);

        __shared__ float fin[8];
        if (lane == 0) fin[wid] = s;
        __syncthreads();
        if (t < 4) {
            const float tot = fin[t] + fin[t + 4];
            out[t] = (t < 3) ? (tot / (float)BB)
                             : (tot / (float)(BB * NNEG));
        }
        if (t == 0) g_count = 0;   // reset for next graph replay
    }
}

extern "C" void kernel_launch(void* const* d_in, const int* in_sizes, int n_in,
                              void* d_out, int out_size)
{
    const float* sparse  = (const float*)d_in[0];
    const int*   ko_ids  = (const int*)d_in[1];
    const int*   ko_len  = (const int*)d_in[2];
    const int*   en_ids  = (const int*)d_in[3];
    const int*   en_len  = (const int*)d_in[4];
    const int*   neg_ids = (const int*)d_in[5];
    float* out = (float*)d_out;

    sort_kernel<<<1, 1024>>>(neg_ids);
    fused_kernel<<<BB, 256>>>(sparse, ko_ids, ko_len, en_ids, en_len, out);
}

// round 15
// speedup vs baseline: 1.6571x; 1.6571x over previous
#include <cuda_runtime.h>
#include <cstdint>

// Problem constants (fixed shapes per reference)
#define BB    256
#define VV    128000
#define LL    32
#define NNEG  1024
#define EPSF  1e-8f
#define TMARG 2.0f
#define NTHR  0.1f

// Flattened quad-work decomposition (1 quad = one int4 of ids = 4 gathers):
//   neg : 256 rows * 256 quads = 65536   (gt in [0, 65536))
//   ko  : 256 rows *   8 quads =  2048   (gt in [65536, 67584))
//   en  : 256 rows *   8 quads =  2048   (gt in [67584, 69632))
// grid = 592 CTAs (= 4 * 148, one perfect wave) * 128 threads = 75776 threads.
// Class boundaries are multiples of 128 -> every CTA is single-class.
#define GRID   592
#define NTHRD  128
#define Q_NEG  65536
#define Q_KO   67584
#define Q_EN   69632

// Deterministic scratch: per-CTA partials [self, target, margin, neg_sum]
__device__ float        g_partial[GRID * 4];
__device__ unsigned int g_count = 0;   // reset by last block -> graph-replay-safe

__global__ __launch_bounds__(NTHRD) void fused_kernel(
    const float* __restrict__ sparse,
    const int*   __restrict__ ko_ids,
    const int*   __restrict__ ko_len,
    const int*   __restrict__ en_ids,
    const int*   __restrict__ en_len,
    const int*   __restrict__ neg_ids,
    float*       __restrict__ out)
{
    const int t  = threadIdx.x;
    const int gt = blockIdx.x * NTHRD + t;

    float v_self = 0.0f, v_tgt = 0.0f, v_mar = 0.0f, v_neg = 0.0f;

    if (gt < Q_NEG) {
        // ---- negative quad: row b, quad t4 (coalesced int4 index load) ----
        const int b  = gt >> 8;
        const int t4 = gt & 255;
        const float* __restrict__ row = sparse + (size_t)b * VV;
        const int4 ids = reinterpret_cast<const int4*>(neg_ids)[t4];
        const float x0 = __ldg(row + ids.x);
        const float x1 = __ldg(row + ids.y);
        const float x2 = __ldg(row + ids.z);
        const float x3 = __ldg(row + ids.w);
        v_neg = fmaxf(x0 - NTHR, 0.0f) + fmaxf(x1 - NTHR, 0.0f)
              + fmaxf(x2 - NTHR, 0.0f) + fmaxf(x3 - NTHR, 0.0f);
    } else if (gt < Q_KO) {
        // ---- ko quad: row b, quad j (elements j*4 .. j*4+3 of 32) ----
        const int q = gt - Q_NEG;
        const int b = q >> 3;
        const int j = q & 7;
        const int kl = ko_len[b];
        const float* __restrict__ row = sparse + (size_t)b * VV;
        const int4 ids = reinterpret_cast<const int4*>(ko_ids)[b * 8 + j];
        const int e0 = j * 4;
        const float a0 = __ldg(row + ids.x);
        const float a1 = __ldg(row + ids.y);
        const float a2 = __ldg(row + ids.z);
        const float a3 = __ldg(row + ids.w);
        float s = 0.0f;
        if (e0 + 0 < kl) s -= __logf(a0 + EPSF);
        if (e0 + 1 < kl) s -= __logf(a1 + EPSF);
        if (e0 + 2 < kl) s -= __logf(a2 + EPSF);
        if (e0 + 3 < kl) s -= __logf(a3 + EPSF);
        // masked_mean: kl==0 -> s==0, so s/max(kl,1)==0 matches jnp.where.
        v_self = s / fmaxf((float)kl, 1.0f);
    } else if (gt < Q_EN) {
        // ---- en quad: -log + margin terms ----
        const int q = gt - Q_KO;
        const int b = q >> 3;
        const int j = q & 7;
        const int el = en_len[b];
        const float* __restrict__ row = sparse + (size_t)b * VV;
        const int4 ids = reinterpret_cast<const int4*>(en_ids)[b * 8 + j];
        const int e0 = j * 4;
        const float a0 = __ldg(row + ids.x);
        const float a1 = __ldg(row + ids.y);
        const float a2 = __ldg(row + ids.z);
        const float a3 = __ldg(row + ids.w);
        float st = 0.0f, sm = 0.0f;
        if (e0 + 0 < el) { st -= __logf(a0 + EPSF); sm += fmaxf(TMARG - a0, 0.0f); }
        if (e0 + 1 < el) { st -= __logf(a1 + EPSF); sm += fmaxf(TMARG - a1, 0.0f); }
        if (e0 + 2 < el) { st -= __logf(a2 + EPSF); sm += fmaxf(TMARG - a2, 0.0f); }
        if (e0 + 3 < el) { st -= __logf(a3 + EPSF); sm += fmaxf(TMARG - a3, 0.0f); }
        const float ce = fmaxf((float)el, 1.0f);
        v_tgt = st / ce;
        v_mar = sm / ce;
    }
    // gt >= Q_EN: idle CTA, zero partials

    // ---- warp reduction (fixed shuffle order -> deterministic) ----
    #pragma unroll
    for (int off = 16; off > 0; off >>= 1) {
        v_self += __shfl_down_sync(0xFFFFFFFFu, v_self, off);
        v_tgt  += __shfl_down_sync(0xFFFFFFFFu, v_tgt,  off);
        v_mar  += __shfl_down_sync(0xFFFFFFFFu, v_mar,  off);
        v_neg  += __shfl_down_sync(0xFFFFFFFFu, v_neg,  off);
    }

    __shared__ float sh[4][4];       // 128 threads = 4 warps
    const int wid = t >> 5;
    if ((t & 31) == 0) {
        sh[wid][0] = v_self;
        sh[wid][1] = v_tgt;
        sh[wid][2] = v_mar;
        sh[wid][3] = v_neg;
    }
    __syncthreads();

    __shared__ bool s_last;
    if (t == 0) {
        float s0 = 0.f, s1 = 0.f, s2 = 0.f, s3 = 0.f;
        #pragma unroll
        for (int w = 0; w < 4; w++) {
            s0 += sh[w][0]; s1 += sh[w][1]; s2 += sh[w][2]; s3 += sh[w][3];
        }
        const int blk = blockIdx.x;
        g_partial[blk * 4 + 0] = s0;
        g_partial[blk * 4 + 1] = s1;
        g_partial[blk * 4 + 2] = s2;
        g_partial[blk * 4 + 3] = s3;
        __threadfence();
        const unsigned int ticket = atomicAdd(&g_count, 1u);
        s_last = (ticket == GRID - 1);
    }
    __syncthreads();

    if (!s_last) return;

    // ---- last block: one-pass final reduce, warp w handles component w ----
    __threadfence();  // acquire all g_partial writes
    {
        const int k    = wid;        // 4 warps, 4 components
        const int lane = t & 31;
        float s = 0.0f;
        #pragma unroll
        for (int i = 0; i < 19; i++) {           // 19*32 = 608 >= 592
            const int p = i * 32 + lane;
            if (p < GRID) s += g_partial[p * 4 + k];
        }
        #pragma unroll
        for (int off = 16; off > 0; off >>= 1)
            s += __shfl_down_sync(0xFFFFFFFFu, s, off);

        if (lane == 0) {
            out[k] = (k < 3) ? (s / (float)BB)
                             : (s / (float)(BB * NNEG));
        }
        if (t == 0) g_count = 0;   // reset for next graph replay
    }
}

extern "C" void kernel_launch(void* const* d_in, const int* in_sizes, int n_in,
                              void* d_out, int out_size)
{
    const float* sparse  = (const float*)d_in[0];
    const int*   ko_ids  = (const int*)d_in[1];
    const int*   ko_len  = (const int*)d_in[2];
    const int*   en_ids  = (const int*)d_in[3];
    const int*   en_len  = (const int*)d_in[4];
    const int*   neg_ids = (const int*)d_in[5];
    float* out = (float*)d_out;

    fused_kernel<<<GRID, NTHRD>>>(sparse, ko_ids, ko_len, en_ids, en_len,
                                  neg_ids, out);
}